// round 1
// baseline (speedup 1.0000x reference)
#include <cuda_runtime.h>
#include <math.h>

#define NN 50000
#define NE 1600000
#define C 128

// ---------------- scratch (device globals; no allocations allowed) ----------------
__device__ float g_h[NN * C];
__device__ float g_hn[NN * C];
__device__ float g_hs[NN * C];
__device__ float g_hd[NN * C];
__device__ float g_hagg[NN * C];
__device__ float g_xagg[NN * 3];
__device__ float g_coord[NN * 3];

__device__ __forceinline__ float silu_f(float x) { return x * (1.f / (1.f + __expf(-x))); }
__device__ __forceinline__ float gelu_f(float x) { return 0.5f * x * (1.f + erff(x * 0.70710678118654752f)); }

__device__ __forceinline__ void red4(float* a, float x, float y, float z, float w) {
    asm volatile("red.global.add.v4.f32 [%0], {%1,%2,%3,%4};"
                 :: "l"(a), "f"(x), "f"(y), "f"(z), "f"(w) : "memory");
}

// block reduce (128 threads) of (v1, v2)
__device__ __forceinline__ float2 blk_red2_128(float v1, float v2, float* s) {
    int lane = threadIdx.x & 31, w = threadIdx.x >> 5;
#pragma unroll
    for (int o = 16; o > 0; o >>= 1) {
        v1 += __shfl_down_sync(0xffffffffu, v1, o);
        v2 += __shfl_down_sync(0xffffffffu, v2, o);
    }
    if (lane == 0) { s[w] = v1; s[4 + w] = v2; }
    __syncthreads();
    float2 r = make_float2(s[0] + s[1] + s[2] + s[3], s[4] + s[5] + s[6] + s[7]);
    __syncthreads();
    return r;
}

// ---------------- embedding: out = gelu(LN(in @ W + b)) ----------------
template <int K>
__global__ __launch_bounds__(128) void embed_kernel(
    const float* __restrict__ in, const float* __restrict__ W, const float* __restrict__ b,
    const float* __restrict__ lg, const float* __restrict__ lb, float* __restrict__ out)
{
    const int R = 4;
    __shared__ float s_in[R * K];
    __shared__ float s_red[8];
    int tid = threadIdx.x;
    int row0 = blockIdx.x * R;
    for (int i = tid; i < R * K; i += 128) s_in[i] = in[row0 * K + i];
    __syncthreads();
    float acc[R];
#pragma unroll
    for (int r = 0; r < R; r++) acc[r] = b[tid];
    for (int k = 0; k < K; k++) {
        float w = W[k * C + tid];
#pragma unroll
        for (int r = 0; r < R; r++) acc[r] += s_in[r * K + k] * w;
    }
    float gg = lg[tid], bb = lb[tid];
#pragma unroll
    for (int r = 0; r < R; r++) {
        float2 sv = blk_red2_128(acc[r], acc[r] * acc[r], s_red);
        float mu = sv.x * (1.f / C);
        float var = sv.y * (1.f / C) - mu * mu;
        float y = (acc[r] - mu) * rsqrtf(var + 1e-5f) * gg + bb;
        out[(row0 + r) * C + tid] = gelu_f(y);
    }
}

// ---------------- per-layer node precompute: hs = h @ ew1[0:128], hd = h @ ew1[128:256] ----------------
__global__ __launch_bounds__(128) void pre_kernel(
    const float* __restrict__ h, const float* __restrict__ ew1,
    float* __restrict__ hs, float* __restrict__ hd)
{
    const int R = 8;
    __shared__ float s_h[R * C];
    int tid = threadIdx.x;
    int row0 = blockIdx.x * R;
    for (int i = tid; i < R * C; i += 128) s_h[i] = h[row0 * C + i];
    __syncthreads();
    float a[R], d[R];
#pragma unroll
    for (int r = 0; r < R; r++) { a[r] = 0.f; d[r] = 0.f; }
    for (int k = 0; k < C; k++) {
        float ws = ew1[k * C + tid], wd = ew1[(C + k) * C + tid];
#pragma unroll
        for (int r = 0; r < R; r++) { float x = s_h[r * C + k]; a[r] += x * ws; d[r] += x * wd; }
    }
#pragma unroll
    for (int r = 0; r < R; r++) {
        hs[(row0 + r) * C + tid] = a[r];
        hd[(row0 + r) * C + tid] = d[r];
    }
}

// ---------------- fused edge kernel ----------------
// per edge: m1 = silu(hs[src] + hd[dst] + radial*w_r + eb1)
//           m2 = silu(m1 @ ew2 + eb2)               -> red into hagg[dst]
// if DO_COORD: t = silu(m2 @ cw1 + cb1); cm = t.cw2 -> red cm*xdiff_norm into xagg[dst]
template <bool DO_COORD>
__global__ __launch_bounds__(512, 1) void edge_kernel(
    const int* __restrict__ src, const int* __restrict__ dst,
    const float* __restrict__ X,
    const float* __restrict__ hs, const float* __restrict__ hd,
    const float* __restrict__ wr, const float* __restrict__ eb1,
    const float* __restrict__ ew2, const float* __restrict__ eb2,
    const float* __restrict__ cw1, const float* __restrict__ cb1,
    const float* __restrict__ cw2,
    float* __restrict__ hagg, float* __restrict__ xagg)
{
    extern __shared__ float sm[];
    float* s_w2 = sm;                    // 16384
    float* s_c1 = sm + C * C;            // 16384
    float* s_stage = sm + 2 * C * C;     // 16 warps * 512
    float* s_vec = s_stage + 16 * 512;   // 5*128
    int tid = threadIdx.x;
    for (int i = tid; i < C * C; i += blockDim.x) s_w2[i] = ew2[i];
    if (DO_COORD)
        for (int i = tid; i < C * C; i += blockDim.x) s_c1[i] = cw1[i];
    if (tid < C) {
        s_vec[tid] = wr[tid];
        s_vec[C + tid] = eb1[tid];
        s_vec[2 * C + tid] = eb2[tid];
        s_vec[3 * C + tid] = cb1[tid];
        s_vec[4 * C + tid] = cw2[tid];
    }
    __syncthreads();
    int warp = tid >> 5, lane = tid & 31;
    float* st = s_stage + warp * 512;        // [128][4] per warp
    float4* st4 = (float4*)st;
    int j0 = lane * 4;
    const int ntiles = NE / 64;

    for (int tile = blockIdx.x; tile < ntiles; tile += gridDim.x) {
        int e0 = tile * 64 + warp * 4;
        int si[4], di[4];
        float dx[4], dy[4], dz[4], rad[4], inv[4];
#pragma unroll
        for (int u = 0; u < 4; u++) {
            int e = e0 + u;
            si[u] = src[e]; di[u] = dst[e];
            float ax = X[si[u] * 3 + 0], ay = X[si[u] * 3 + 1], az = X[si[u] * 3 + 2];
            float bx = X[di[u] * 3 + 0], by = X[di[u] * 3 + 1], bz = X[di[u] * 3 + 2];
            dx[u] = ax - bx; dy[u] = ay - by; dz[u] = az - bz;
            rad[u] = dx[u] * dx[u] + dy[u] * dy[u] + dz[u] * dz[u];
            inv[u] = 1.f / (sqrtf(rad[u]) + 1e-30f);
        }
        // m1 -> stage [k][u]
#pragma unroll
        for (int q = 0; q < 4; q++) {
            int c = lane + 32 * q;
            float w = s_vec[c], b1 = s_vec[C + c];
#pragma unroll
            for (int u = 0; u < 4; u++) {
                float v = hs[(size_t)si[u] * C + c] + hd[(size_t)di[u] * C + c] + rad[u] * w + b1;
                st[c * 4 + u] = silu_f(v);
            }
        }
        __syncwarp();
        // m2 = silu(m1 @ ew2 + eb2); thread owns cols j0..j0+3
        float acc[4][4];
#pragma unroll
        for (int i = 0; i < 4; i++) {
            float b2 = s_vec[2 * C + j0 + i];
#pragma unroll
            for (int u = 0; u < 4; u++) acc[u][i] = b2;
        }
        const float4* w2row = (const float4*)s_w2;
#pragma unroll 4
        for (int k = 0; k < C; k++) {
            float4 wv = w2row[k * 32 + lane];
            float4 mv = st4[k];
            acc[0][0] += mv.x * wv.x; acc[0][1] += mv.x * wv.y; acc[0][2] += mv.x * wv.z; acc[0][3] += mv.x * wv.w;
            acc[1][0] += mv.y * wv.x; acc[1][1] += mv.y * wv.y; acc[1][2] += mv.y * wv.z; acc[1][3] += mv.y * wv.w;
            acc[2][0] += mv.z * wv.x; acc[2][1] += mv.z * wv.y; acc[2][2] += mv.z * wv.z; acc[2][3] += mv.z * wv.w;
            acc[3][0] += mv.w * wv.x; acc[3][1] += mv.w * wv.y; acc[3][2] += mv.w * wv.z; acc[3][3] += mv.w * wv.w;
        }
        float m2r[4][4];
#pragma unroll
        for (int u = 0; u < 4; u++)
#pragma unroll
            for (int i = 0; i < 4; i++) m2r[u][i] = silu_f(acc[u][i]);

        if (DO_COORD) {
            __syncwarp();
#pragma unroll
            for (int i = 0; i < 4; i++)
                st4[j0 + i] = make_float4(m2r[0][i], m2r[1][i], m2r[2][i], m2r[3][i]);
            __syncwarp();
            float acct[4][4];
#pragma unroll
            for (int i = 0; i < 4; i++) {
                float cb = s_vec[3 * C + j0 + i];
#pragma unroll
                for (int u = 0; u < 4; u++) acct[u][i] = cb;
            }
            const float4* c1row = (const float4*)s_c1;
#pragma unroll 4
            for (int k = 0; k < C; k++) {
                float4 wv = c1row[k * 32 + lane];
                float4 mv = st4[k];
                acct[0][0] += mv.x * wv.x; acct[0][1] += mv.x * wv.y; acct[0][2] += mv.x * wv.z; acct[0][3] += mv.x * wv.w;
                acct[1][0] += mv.y * wv.x; acct[1][1] += mv.y * wv.y; acct[1][2] += mv.y * wv.z; acct[1][3] += mv.y * wv.w;
                acct[2][0] += mv.z * wv.x; acct[2][1] += mv.z * wv.y; acct[2][2] += mv.z * wv.z; acct[2][3] += mv.z * wv.w;
                acct[3][0] += mv.w * wv.x; acct[3][1] += mv.w * wv.y; acct[3][2] += mv.w * wv.z; acct[3][3] += mv.w * wv.w;
            }
            float4 cwv = ((const float4*)(s_vec + 4 * C))[lane];
            float p[4];
#pragma unroll
            for (int u = 0; u < 4; u++) {
                p[u] = silu_f(acct[u][0]) * cwv.x + silu_f(acct[u][1]) * cwv.y
                     + silu_f(acct[u][2]) * cwv.z + silu_f(acct[u][3]) * cwv.w;
#pragma unroll
                for (int o = 16; o > 0; o >>= 1) p[u] += __shfl_down_sync(0xffffffffu, p[u], o);
            }
            if (lane == 0) {
#pragma unroll
                for (int u = 0; u < 4; u++) {
                    float s = p[u] * inv[u];
                    atomicAdd(&xagg[di[u] * 3 + 0], s * dx[u]);
                    atomicAdd(&xagg[di[u] * 3 + 1], s * dy[u]);
                    atomicAdd(&xagg[di[u] * 3 + 2], s * dz[u]);
                }
            }
        }
        // aggregate m2 into hagg[dst]
#pragma unroll
        for (int u = 0; u < 4; u++)
            red4(&hagg[(size_t)di[u] * C + j0], m2r[u][0], m2r[u][1], m2r[u][2], m2r[u][3]);
        __syncwarp();  // protect stage before next tile
    }
}

// ---------------- node update (+ optional gelu->LN for decoder layers) ----------------
template <bool DEC>
__global__ __launch_bounds__(128) void node_kernel(
    const float* __restrict__ h, const float* __restrict__ hagg,
    const float* __restrict__ nw1, const float* __restrict__ nb1,
    const float* __restrict__ nw2, const float* __restrict__ nb2,
    const float* __restrict__ lg, const float* __restrict__ lb,
    float* __restrict__ out)
{
    const int R = 8;
    __shared__ float s_h[R * C], s_a[R * C], s_u[R * C];
    __shared__ float s_red[8];
    int tid = threadIdx.x;
    int row0 = blockIdx.x * R;
    for (int i = tid; i < R * C; i += 128) { s_h[i] = h[row0 * C + i]; s_a[i] = hagg[row0 * C + i]; }
    __syncthreads();
    float acc[R];
#pragma unroll
    for (int r = 0; r < R; r++) acc[r] = nb1[tid];
    for (int k = 0; k < C; k++) {
        float wa = nw1[k * C + tid], wb = nw1[(C + k) * C + tid];
#pragma unroll
        for (int r = 0; r < R; r++) acc[r] += s_h[r * C + k] * wa + s_a[r * C + k] * wb;
    }
#pragma unroll
    for (int r = 0; r < R; r++) s_u[r * C + tid] = silu_f(acc[r]);
    __syncthreads();
    float o[R];
#pragma unroll
    for (int r = 0; r < R; r++) o[r] = nb2[tid];
    for (int k = 0; k < C; k++) {
        float w = nw2[k * C + tid];
#pragma unroll
        for (int r = 0; r < R; r++) o[r] += s_u[r * C + k] * w;
    }
    if (DEC) {
        float gg = lg[tid], bb = lb[tid];
#pragma unroll
        for (int r = 0; r < R; r++) {
            float x = gelu_f(o[r]);
            float2 sv = blk_red2_128(x, x * x, s_red);
            float mu = sv.x * (1.f / C);
            float var = sv.y * (1.f / C) - mu * mu;
            o[r] = (x - mu) * rsqrtf(var + 1e-5f) * gg + bb;
        }
    }
#pragma unroll
    for (int r = 0; r < R; r++) out[(row0 + r) * C + tid] = o[r];
}

__global__ void coord_add_kernel(const float* __restrict__ xyz, const float* __restrict__ xagg,
                                 float* __restrict__ coord)
{
    int i = blockIdx.x * 256 + threadIdx.x;
    if (i < NN * 3) coord[i] = xyz[i] + xagg[i];
}

__global__ __launch_bounds__(256) void out_kernel(
    const float* __restrict__ h, const float* __restrict__ W,
    const float* __restrict__ b, float* __restrict__ out)
{
    int n = blockIdx.x * 8 + (threadIdx.x >> 5);
    if (n >= NN) return;
    int lane = threadIdx.x & 31;
    float a0 = 0.f, a1 = 0.f, a2 = 0.f;
#pragma unroll
    for (int q = 0; q < 4; q++) {
        int k = lane + 32 * q;
        float x = h[(size_t)n * C + k];
        a0 += x * W[k * 3 + 0]; a1 += x * W[k * 3 + 1]; a2 += x * W[k * 3 + 2];
    }
#pragma unroll
    for (int o = 16; o > 0; o >>= 1) {
        a0 += __shfl_down_sync(0xffffffffu, a0, o);
        a1 += __shfl_down_sync(0xffffffffu, a1, o);
        a2 += __shfl_down_sync(0xffffffffu, a2, o);
    }
    if (lane == 0) {
        out[n * 3 + 0] = a0 + b[0];
        out[n * 3 + 1] = a1 + b[1];
        out[n * 3 + 2] = a2 + b[2];
    }
}

extern "C" void kernel_launch(void* const* d_in, const int* in_sizes, int n_in,
                              void* d_out, int out_size)
{
    const int*   src       = (const int*)d_in[0];
    const int*   dst       = (const int*)d_in[1];
    const float* node_attr = (const float*)d_in[2];
    const float* xyz       = (const float*)d_in[3];
    const float* emb_w1    = (const float*)d_in[4];
    const float* emb_b1    = (const float*)d_in[5];
    const float* ln1_g     = (const float*)d_in[6];
    const float* ln1_b     = (const float*)d_in[7];
    const float* emb_w2    = (const float*)d_in[8];
    const float* emb_b2    = (const float*)d_in[9];
    const float* ln2_g     = (const float*)d_in[10];
    const float* ln2_b     = (const float*)d_in[11];
    const float* e_w1      = (const float*)d_in[12];
    const float* e_b1      = (const float*)d_in[13];
    const float* e_w2      = (const float*)d_in[14];
    const float* e_b2      = (const float*)d_in[15];
    const float* n_w1      = (const float*)d_in[16];
    const float* n_b1      = (const float*)d_in[17];
    const float* n_w2      = (const float*)d_in[18];
    const float* n_b2      = (const float*)d_in[19];
    const float* c_w1      = (const float*)d_in[20];
    const float* c_b1      = (const float*)d_in[21];
    const float* c_w2      = (const float*)d_in[22];
    const float* dec_ln_g  = (const float*)d_in[23];
    const float* dec_ln_b  = (const float*)d_in[24];
    const float* out_w     = (const float*)d_in[25];
    const float* out_b     = (const float*)d_in[26];
    float* out = (float*)d_out;

    float *h, *hn, *hs, *hd, *hagg, *xagg, *coord;
    cudaGetSymbolAddress((void**)&h, g_h);
    cudaGetSymbolAddress((void**)&hn, g_hn);
    cudaGetSymbolAddress((void**)&hs, g_hs);
    cudaGetSymbolAddress((void**)&hd, g_hd);
    cudaGetSymbolAddress((void**)&hagg, g_hagg);
    cudaGetSymbolAddress((void**)&xagg, g_xagg);
    cudaGetSymbolAddress((void**)&coord, g_coord);

    int dev = 0;
    cudaGetDevice(&dev);
    int nsm = 148;
    cudaDeviceGetAttribute(&nsm, cudaDevAttrMultiProcessorCount, dev);

    const int SMEM_EDGE = (2 * C * C + 16 * 512 + 5 * C) * (int)sizeof(float);
    cudaFuncSetAttribute((const void*)edge_kernel<true>,
                         cudaFuncAttributeMaxDynamicSharedMemorySize, SMEM_EDGE);
    cudaFuncSetAttribute((const void*)edge_kernel<false>,
                         cudaFuncAttributeMaxDynamicSharedMemorySize, SMEM_EDGE);

    // initial node embedding
    embed_kernel<64><<<NN / 4, 128>>>(node_attr, emb_w1, emb_b1, ln1_g, ln1_b, hn);
    embed_kernel<128><<<NN / 4, 128>>>(hn, emb_w2, emb_b2, ln2_g, ln2_b, h);

    float* hcur = h;
    float* htmp = hn;
    for (int l = 0; l < 3; l++) {
        const float* ew1l = e_w1 + (size_t)l * 257 * C;
        pre_kernel<<<NN / 8, 128>>>(hcur, ew1l, hs, hd);
        cudaMemsetAsync(hagg, 0, (size_t)NN * C * sizeof(float));
        const float* Xl = (l == 2) ? coord : xyz;
        if (l == 1) {
            cudaMemsetAsync(xagg, 0, (size_t)NN * 3 * sizeof(float));
            edge_kernel<true><<<nsm, 512, SMEM_EDGE>>>(
                src, dst, Xl, hs, hd, ew1l + 256 * C, e_b1 + l * C,
                e_w2 + (size_t)l * C * C, e_b2 + l * C,
                c_w1 + (size_t)l * C * C, c_b1 + l * C, c_w2 + l * C, hagg, xagg);
        } else {
            edge_kernel<false><<<nsm, 512, SMEM_EDGE>>>(
                src, dst, Xl, hs, hd, ew1l + 256 * C, e_b1 + l * C,
                e_w2 + (size_t)l * C * C, e_b2 + l * C,
                c_w1 + (size_t)l * C * C, c_b1 + l * C, c_w2 + l * C, hagg, xagg);
        }
        if (l == 0)
            node_kernel<false><<<NN / 8, 128>>>(hcur, hagg,
                n_w1 + (size_t)l * 256 * C, n_b1 + l * C,
                n_w2 + (size_t)l * C * C, n_b2 + l * C, dec_ln_g, dec_ln_b, htmp);
        else
            node_kernel<true><<<NN / 8, 128>>>(hcur, hagg,
                n_w1 + (size_t)l * 256 * C, n_b1 + l * C,
                n_w2 + (size_t)l * C * C, n_b2 + l * C, dec_ln_g, dec_ln_b, htmp);
        float* t = hcur; hcur = htmp; htmp = t;
        if (l == 1) coord_add_kernel<<<(NN * 3 + 255) / 256, 256>>>(xyz, xagg, coord);
    }
    out_kernel<<<(NN + 7) / 8, 256>>>(hcur, out_w, out_b, out);
}

// round 5
// speedup vs baseline: 1.2752x; 1.2752x over previous
#include <cuda_runtime.h>
#include <cuda_bf16.h>
#include <math.h>
#include <stdint.h>

#define NN 50000
#define NE 1600000
#define C 128
#define ETILE 128
#define NTILES (NE / ETILE)
#define AST 136               // bf16 elements per smem tile row (odd multiple of 8 -> conflict-free ldmatrix)
#define ASTB (AST * 2)        // bytes per row = 272

// ---------------- scratch ----------------
__device__ float g_h[NN * C];
__device__ float g_hn[NN * C];
__device__ float g_hs[NN * C];
__device__ float g_hd[NN * C];
__device__ float g_hagg[NN * C];
__device__ float g_xagg[NN * 3];
__device__ float g_coord[NN * 3];

__device__ __forceinline__ float silu_f(float x) { return x * (1.f / (1.f + __expf(-x))); }
__device__ __forceinline__ float gelu_f(float x) { return 0.5f * x * (1.f + erff(x * 0.70710678118654752f)); }

__device__ __forceinline__ void red2(float* a, float x, float y) {
    asm volatile("red.global.add.v2.f32 [%0], {%1,%2};" :: "l"(a), "f"(x), "f"(y) : "memory");
}
__device__ __forceinline__ uint32_t smem_u32(const void* p) {
    uint32_t a;
    asm("{ .reg .u64 t; cvta.to.shared.u64 t, %1; cvt.u32.u64 %0, t; }" : "=r"(a) : "l"(p));
    return a;
}
__device__ __forceinline__ void ldm_x4(uint32_t& r0, uint32_t& r1, uint32_t& r2, uint32_t& r3, uint32_t addr) {
    asm volatile("ldmatrix.sync.aligned.m8n8.x4.shared.b16 {%0,%1,%2,%3}, [%4];"
                 : "=r"(r0), "=r"(r1), "=r"(r2), "=r"(r3) : "r"(addr));
}
__device__ __forceinline__ void mma_bf16(float* c, uint32_t a0, uint32_t a1, uint32_t a2, uint32_t a3,
                                         uint32_t b0, uint32_t b1) {
    asm volatile("mma.sync.aligned.m16n8k16.row.col.f32.bf16.bf16.f32 "
                 "{%0,%1,%2,%3},{%4,%5,%6,%7},{%8,%9},{%0,%1,%2,%3};"
                 : "+f"(c[0]), "+f"(c[1]), "+f"(c[2]), "+f"(c[3])
                 : "r"(a0), "r"(a1), "r"(a2), "r"(a3), "r"(b0), "r"(b1));
}

// store fp32 pair as bf16 hi/lo split into row-major [128][AST] tiles
__device__ __forceinline__ void st_split(char* smem, uint32_t offH, uint32_t offL,
                                         int r, int c, float v0, float v1) {
    uint32_t o = (uint32_t)(r * ASTB + c * 2);
    __nv_bfloat162 hi, lo;
    hi.x = __float2bfloat16(v0);
    hi.y = __float2bfloat16(v1);
    lo.x = __float2bfloat16(v0 - __bfloat162float(hi.x));
    lo.y = __float2bfloat16(v1 - __bfloat162float(hi.y));
    *(__nv_bfloat162*)(smem + offH + o) = hi;
    *(__nv_bfloat162*)(smem + offL + o) = lo;
}

// one bf16 MMA pass: acc += A[128xK=128] @ B^T (B stored [n][k]), warp (wm, wn), m16 x n64 per warp
__device__ __forceinline__ void mma_pass(float acc[8][4], uint32_t sb, uint32_t aoff, uint32_t boff,
                                         int wm, int wn, int lane) {
    uint32_t a_base = sb + aoff + (uint32_t)((wm * 16 + (lane & 15)) * ASTB + ((lane >> 4) << 3) * 2);
    uint32_t b_base = sb + boff + (uint32_t)((wn * 64 + ((lane >> 4) << 3) + (lane & 7)) * ASTB
                                             + (((lane >> 3) & 1) << 3) * 2);
#pragma unroll
    for (int k8 = 0; k8 < 8; k8++) {
        uint32_t a0, a1, a2, a3;
        ldm_x4(a0, a1, a2, a3, a_base + k8 * 32);
#pragma unroll
        for (int j4 = 0; j4 < 4; j4++) {
            uint32_t b0, b1, b2, b3;
            ldm_x4(b0, b1, b2, b3, b_base + (uint32_t)(j4 * 16 * ASTB) + k8 * 32);
            mma_bf16(acc[2 * j4], a0, a1, a2, a3, b0, b1);
            mma_bf16(acc[2 * j4 + 1], a0, a1, a2, a3, b2, b3);
        }
    }
}

// smem layout (bytes)
#define OFF_VEC  0
#define OFF_GEO  2560
#define OFF_CM   4608
#define OFF_AHI  5120
#define TILE_B   (128 * ASTB)          // 34816
#define OFF_ALO  (OFF_AHI + TILE_B)
#define OFF_B1H  (OFF_ALO + TILE_B)
#define OFF_B1L  (OFF_B1H + TILE_B)
#define OFF_B2H  (OFF_B1L + TILE_B)
#define OFF_B2L  (OFF_B2H + TILE_B)
#define SMEM_EDGE_NC (OFF_B1L + TILE_B)
#define SMEM_EDGE_CO (OFF_B2L + TILE_B)

// ---------------- fused edge kernel (mma.sync bf16 3-pass) ----------------
template <bool DO_COORD>
__global__ __launch_bounds__(512, 1) void edge_mma_kernel(
    const int* __restrict__ src, const int* __restrict__ dst,
    const float* __restrict__ X,
    const float* __restrict__ hs, const float* __restrict__ hd,
    const float* __restrict__ wr, const float* __restrict__ eb1,
    const float* __restrict__ ew2, const float* __restrict__ eb2,
    const float* __restrict__ cw1, const float* __restrict__ cb1,
    const float* __restrict__ cw2,
    float* __restrict__ hagg, float* __restrict__ xagg)
{
    extern __shared__ char smem[];
    uint32_t sb = smem_u32(smem);
    float* s_vec = (float*)(smem + OFF_VEC);
    float4* s_geo = (float4*)(smem + OFF_GEO);
    float* s_cm = (float*)(smem + OFF_CM);
    int tid = threadIdx.x, warp = tid >> 5, lane = tid & 31;
    int wm = warp >> 1, wn = warp & 1;

    if (tid < C) {
        s_vec[tid] = wr[tid];
        s_vec[C + tid] = eb1[tid];
        s_vec[2 * C + tid] = eb2[tid];
        if (DO_COORD) { s_vec[3 * C + tid] = cb1[tid]; s_vec[4 * C + tid] = cw2[tid]; }
    }
    if (DO_COORD && tid < ETILE) s_cm[tid] = 0.f;
    // stationary weights: Bs[n][k] = W[k][n], bf16 hi/lo
    for (int idx = tid; idx < C * C; idx += 512) {
        int n = idx >> 7, k = idx & 127;
        uint32_t o = (uint32_t)(n * ASTB + k * 2);
        float w = ew2[k * C + n];
        __nv_bfloat16 h1 = __float2bfloat16(w);
        *(__nv_bfloat16*)(smem + OFF_B1H + o) = h1;
        *(__nv_bfloat16*)(smem + OFF_B1L + o) = __float2bfloat16(w - __bfloat162float(h1));
        if (DO_COORD) {
            float w2 = cw1[k * C + n];
            __nv_bfloat16 h2 = __float2bfloat16(w2);
            *(__nv_bfloat16*)(smem + OFF_B2H + o) = h2;
            *(__nv_bfloat16*)(smem + OFF_B2L + o) = __float2bfloat16(w2 - __bfloat162float(h2));
        }
    }
    __syncthreads();

    int el = tid >> 2, cg = (tid & 3) << 5;     // m1 phase: edge row, col group
    int g = lane >> 2, q4 = lane & 3;           // fragment row/col ids

    for (int tile = blockIdx.x; tile < NTILES; tile += gridDim.x) {
        // ---- m1 = silu(hs[src] + hd[dst] + rad*wr + eb1) -> A tiles ----
        {
            int e = tile * ETILE + el;
            int si = src[e], di = dst[e];
            float ax = X[si * 3 + 0] - X[di * 3 + 0];
            float ay = X[si * 3 + 1] - X[di * 3 + 1];
            float az = X[si * 3 + 2] - X[di * 3 + 2];
            float rad = ax * ax + ay * ay + az * az;
            if (DO_COORD && (tid & 3) == 0)
                s_geo[el] = make_float4(ax, ay, az, 1.f / (sqrtf(rad) + 1e-30f));
            const float4* ps = (const float4*)(hs + (size_t)si * C + cg);
            const float4* pd = (const float4*)(hd + (size_t)di * C + cg);
#pragma unroll
            for (int qq = 0; qq < 8; qq++) {
                float4 a = ps[qq], b = pd[qq];
                int c = cg + qq * 4;
                float v0 = silu_f(a.x + b.x + rad * s_vec[c + 0] + s_vec[C + c + 0]);
                float v1 = silu_f(a.y + b.y + rad * s_vec[c + 1] + s_vec[C + c + 1]);
                float v2 = silu_f(a.z + b.z + rad * s_vec[c + 2] + s_vec[C + c + 2]);
                float v3 = silu_f(a.w + b.w + rad * s_vec[c + 3] + s_vec[C + c + 3]);
                st_split(smem, OFF_AHI, OFF_ALO, el, c, v0, v1);
                st_split(smem, OFF_AHI, OFF_ALO, el, c + 2, v2, v3);
            }
        }
        __syncthreads();
        // ---- MMA1: D1 = m1 @ ew2 (3-pass split) ----
        float acc[8][4];
#pragma unroll
        for (int j = 0; j < 8; j++) { acc[j][0] = acc[j][1] = acc[j][2] = acc[j][3] = 0.f; }
        mma_pass(acc, sb, OFF_AHI, OFF_B1H, wm, wn, lane);
        mma_pass(acc, sb, OFF_AHI, OFF_B1L, wm, wn, lane);
        mma_pass(acc, sb, OFF_ALO, OFF_B1H, wm, wn, lane);
        __syncthreads();   // all warps done reading A tiles
        // ---- epilogue 1: m2 = silu(D1 + eb2) -> hagg atomics (+ restage for MMA2) ----
        {
            int r0 = wm * 16 + g, r1 = r0 + 8;
            int d0 = dst[tile * ETILE + r0], d1 = dst[tile * ETILE + r1];
            float* h0 = hagg + (size_t)d0 * C;
            float* h1 = hagg + (size_t)d1 * C;
#pragma unroll
            for (int j = 0; j < 8; j++) {
                int col = wn * 64 + j * 8 + q4 * 2;
                float b0 = s_vec[2 * C + col], b1 = s_vec[2 * C + col + 1];
                float m00 = silu_f(acc[j][0] + b0), m01 = silu_f(acc[j][1] + b1);
                float m10 = silu_f(acc[j][2] + b0), m11 = silu_f(acc[j][3] + b1);
                red2(h0 + col, m00, m01);
                red2(h1 + col, m10, m11);
                if (DO_COORD) {
                    st_split(smem, OFF_AHI, OFF_ALO, r0, col, m00, m01);
                    st_split(smem, OFF_AHI, OFF_ALO, r1, col, m10, m11);
                }
            }
        }
        if (DO_COORD) {
            __syncthreads();
            // ---- MMA2: D2 = m2 @ cw1 ----
#pragma unroll
            for (int j = 0; j < 8; j++) { acc[j][0] = acc[j][1] = acc[j][2] = acc[j][3] = 0.f; }
            mma_pass(acc, sb, OFF_AHI, OFF_B2H, wm, wn, lane);
            mma_pass(acc, sb, OFF_AHI, OFF_B2L, wm, wn, lane);
            mma_pass(acc, sb, OFF_ALO, OFF_B2H, wm, wn, lane);
            // ---- epilogue 2: cm = sum_c silu(D2 + cb1) * cw2 ----
            {
                float p0 = 0.f, p1 = 0.f;
#pragma unroll
                for (int j = 0; j < 8; j++) {
                    int col = wn * 64 + j * 8 + q4 * 2;
                    float cb0 = s_vec[3 * C + col], cb1v = s_vec[3 * C + col + 1];
                    float w0 = s_vec[4 * C + col], w1 = s_vec[4 * C + col + 1];
                    p0 += silu_f(acc[j][0] + cb0) * w0 + silu_f(acc[j][1] + cb1v) * w1;
                    p1 += silu_f(acc[j][2] + cb0) * w0 + silu_f(acc[j][3] + cb1v) * w1;
                }
                int r0 = wm * 16 + g;
                atomicAdd(&s_cm[r0], p0);
                atomicAdd(&s_cm[r0 + 8], p1);
            }
            __syncthreads();
            if (tid < ETILE) {
                float cm = s_cm[tid];
                s_cm[tid] = 0.f;
                float4 gg = s_geo[tid];
                int d2 = dst[tile * ETILE + tid];
                float s = cm * gg.w;
                atomicAdd(&xagg[d2 * 3 + 0], s * gg.x);
                atomicAdd(&xagg[d2 * 3 + 1], s * gg.y);
                atomicAdd(&xagg[d2 * 3 + 2], s * gg.z);
            }
            __syncthreads();
        }
    }
}

// ---------------- node-side kernels (unchanged, proven) ----------------
__device__ __forceinline__ float2 blk_red2_128(float v1, float v2, float* s) {
    int lane = threadIdx.x & 31, w = threadIdx.x >> 5;
#pragma unroll
    for (int o = 16; o > 0; o >>= 1) {
        v1 += __shfl_down_sync(0xffffffffu, v1, o);
        v2 += __shfl_down_sync(0xffffffffu, v2, o);
    }
    if (lane == 0) { s[w] = v1; s[4 + w] = v2; }
    __syncthreads();
    float2 r = make_float2(s[0] + s[1] + s[2] + s[3], s[4] + s[5] + s[6] + s[7]);
    __syncthreads();
    return r;
}

template <int K>
__global__ __launch_bounds__(128) void embed_kernel(
    const float* __restrict__ in, const float* __restrict__ W, const float* __restrict__ b,
    const float* __restrict__ lg, const float* __restrict__ lb, float* __restrict__ out)
{
    const int R = 4;
    __shared__ float s_in[R * K];
    __shared__ float s_red[8];
    int tid = threadIdx.x;
    int row0 = blockIdx.x * R;
    for (int i = tid; i < R * K; i += 128) s_in[i] = in[row0 * K + i];
    __syncthreads();
    float acc[R];
#pragma unroll
    for (int r = 0; r < R; r++) acc[r] = b[tid];
    for (int k = 0; k < K; k++) {
        float w = W[k * C + tid];
#pragma unroll
        for (int r = 0; r < R; r++) acc[r] += s_in[r * K + k] * w;
    }
    float gg = lg[tid], bb = lb[tid];
#pragma unroll
    for (int r = 0; r < R; r++) {
        float2 sv = blk_red2_128(acc[r], acc[r] * acc[r], s_red);
        float mu = sv.x * (1.f / C);
        float var = sv.y * (1.f / C) - mu * mu;
        float y = (acc[r] - mu) * rsqrtf(var + 1e-5f) * gg + bb;
        out[(row0 + r) * C + tid] = gelu_f(y);
    }
}

__global__ __launch_bounds__(128) void pre_kernel(
    const float* __restrict__ h, const float* __restrict__ ew1,
    float* __restrict__ hs, float* __restrict__ hd)
{
    const int R = 8;
    __shared__ float s_h[R * C];
    int tid = threadIdx.x;
    int row0 = blockIdx.x * R;
    for (int i = tid; i < R * C; i += 128) s_h[i] = h[row0 * C + i];
    __syncthreads();
    float a[R], d[R];
#pragma unroll
    for (int r = 0; r < R; r++) { a[r] = 0.f; d[r] = 0.f; }
    for (int k = 0; k < C; k++) {
        float ws = ew1[k * C + tid], wd = ew1[(C + k) * C + tid];
#pragma unroll
        for (int r = 0; r < R; r++) { float x = s_h[r * C + k]; a[r] += x * ws; d[r] += x * wd; }
    }
#pragma unroll
    for (int r = 0; r < R; r++) {
        hs[(row0 + r) * C + tid] = a[r];
        hd[(row0 + r) * C + tid] = d[r];
    }
}

template <bool DEC>
__global__ __launch_bounds__(128) void node_kernel(
    const float* __restrict__ h, const float* __restrict__ hagg,
    const float* __restrict__ nw1, const float* __restrict__ nb1,
    const float* __restrict__ nw2, const float* __restrict__ nb2,
    const float* __restrict__ lg, const float* __restrict__ lb,
    float* __restrict__ out)
{
    const int R = 8;
    __shared__ float s_h[R * C], s_a[R * C], s_u[R * C];
    __shared__ float s_red[8];
    int tid = threadIdx.x;
    int row0 = blockIdx.x * R;
    for (int i = tid; i < R * C; i += 128) { s_h[i] = h[row0 * C + i]; s_a[i] = hagg[row0 * C + i]; }
    __syncthreads();
    float acc[R];
#pragma unroll
    for (int r = 0; r < R; r++) acc[r] = nb1[tid];
    for (int k = 0; k < C; k++) {
        float wa = nw1[k * C + tid], wb = nw1[(C + k) * C + tid];
#pragma unroll
        for (int r = 0; r < R; r++) acc[r] += s_h[r * C + k] * wa + s_a[r * C + k] * wb;
    }
#pragma unroll
    for (int r = 0; r < R; r++) s_u[r * C + tid] = silu_f(acc[r]);
    __syncthreads();
    float o[R];
#pragma unroll
    for (int r = 0; r < R; r++) o[r] = nb2[tid];
    for (int k = 0; k < C; k++) {
        float w = nw2[k * C + tid];
#pragma unroll
        for (int r = 0; r < R; r++) o[r] += s_u[r * C + k] * w;
    }
    if (DEC) {
        float gg = lg[tid], bb = lb[tid];
#pragma unroll
        for (int r = 0; r < R; r++) {
            float x = gelu_f(o[r]);
            float2 sv = blk_red2_128(x, x * x, s_red);
            float mu = sv.x * (1.f / C);
            float var = sv.y * (1.f / C) - mu * mu;
            o[r] = (x - mu) * rsqrtf(var + 1e-5f) * gg + bb;
        }
    }
#pragma unroll
    for (int r = 0; r < R; r++) out[(row0 + r) * C + tid] = o[r];
}

__global__ void coord_add_kernel(const float* __restrict__ xyz, const float* __restrict__ xagg,
                                 float* __restrict__ coord)
{
    int i = blockIdx.x * 256 + threadIdx.x;
    if (i < NN * 3) coord[i] = xyz[i] + xagg[i];
}

__global__ __launch_bounds__(256) void out_kernel(
    const float* __restrict__ h, const float* __restrict__ W,
    const float* __restrict__ b, float* __restrict__ out)
{
    int n = blockIdx.x * 8 + (threadIdx.x >> 5);
    if (n >= NN) return;
    int lane = threadIdx.x & 31;
    float a0 = 0.f, a1 = 0.f, a2 = 0.f;
#pragma unroll
    for (int q = 0; q < 4; q++) {
        int k = lane + 32 * q;
        float x = h[(size_t)n * C + k];
        a0 += x * W[k * 3 + 0]; a1 += x * W[k * 3 + 1]; a2 += x * W[k * 3 + 2];
    }
#pragma unroll
    for (int o = 16; o > 0; o >>= 1) {
        a0 += __shfl_down_sync(0xffffffffu, a0, o);
        a1 += __shfl_down_sync(0xffffffffu, a1, o);
        a2 += __shfl_down_sync(0xffffffffu, a2, o);
    }
    if (lane == 0) {
        out[n * 3 + 0] = a0 + b[0];
        out[n * 3 + 1] = a1 + b[1];
        out[n * 3 + 2] = a2 + b[2];
    }
}

extern "C" void kernel_launch(void* const* d_in, const int* in_sizes, int n_in,
                              void* d_out, int out_size)
{
    const int*   src       = (const int*)d_in[0];
    const int*   dst       = (const int*)d_in[1];
    const float* node_attr = (const float*)d_in[2];
    const float* xyz       = (const float*)d_in[3];
    const float* emb_w1    = (const float*)d_in[4];
    const float* emb_b1    = (const float*)d_in[5];
    const float* ln1_g     = (const float*)d_in[6];
    const float* ln1_b     = (const float*)d_in[7];
    const float* emb_w2    = (const float*)d_in[8];
    const float* emb_b2    = (const float*)d_in[9];
    const float* ln2_g     = (const float*)d_in[10];
    const float* ln2_b     = (const float*)d_in[11];
    const float* e_w1      = (const float*)d_in[12];
    const float* e_b1      = (const float*)d_in[13];
    const float* e_w2      = (const float*)d_in[14];
    const float* e_b2      = (const float*)d_in[15];
    const float* n_w1      = (const float*)d_in[16];
    const float* n_b1      = (const float*)d_in[17];
    const float* n_w2      = (const float*)d_in[18];
    const float* n_b2      = (const float*)d_in[19];
    const float* c_w1      = (const float*)d_in[20];
    const float* c_b1      = (const float*)d_in[21];
    const float* c_w2      = (const float*)d_in[22];
    const float* dec_ln_g  = (const float*)d_in[23];
    const float* dec_ln_b  = (const float*)d_in[24];
    const float* out_w     = (const float*)d_in[25];
    const float* out_b     = (const float*)d_in[26];
    float* out = (float*)d_out;

    float *h, *hn, *hs, *hd, *hagg, *xagg, *coord;
    cudaGetSymbolAddress((void**)&h, g_h);
    cudaGetSymbolAddress((void**)&hn, g_hn);
    cudaGetSymbolAddress((void**)&hs, g_hs);
    cudaGetSymbolAddress((void**)&hd, g_hd);
    cudaGetSymbolAddress((void**)&hagg, g_hagg);
    cudaGetSymbolAddress((void**)&xagg, g_xagg);
    cudaGetSymbolAddress((void**)&coord, g_coord);

    int dev = 0;
    cudaGetDevice(&dev);
    int nsm = 148;
    cudaDeviceGetAttribute(&nsm, cudaDevAttrMultiProcessorCount, dev);

    cudaFuncSetAttribute((const void*)edge_mma_kernel<false>,
                         cudaFuncAttributeMaxDynamicSharedMemorySize, SMEM_EDGE_NC);
    cudaFuncSetAttribute((const void*)edge_mma_kernel<true>,
                         cudaFuncAttributeMaxDynamicSharedMemorySize, SMEM_EDGE_CO);

    // initial node embedding
    embed_kernel<64><<<NN / 4, 128>>>(node_attr, emb_w1, emb_b1, ln1_g, ln1_b, hn);
    embed_kernel<128><<<NN / 4, 128>>>(hn, emb_w2, emb_b2, ln2_g, ln2_b, h);

    float* hcur = h;
    float* htmp = hn;
    for (int l = 0; l < 3; l++) {
        const float* ew1l = e_w1 + (size_t)l * 257 * C;
        pre_kernel<<<NN / 8, 128>>>(hcur, ew1l, hs, hd);
        cudaMemsetAsync(hagg, 0, (size_t)NN * C * sizeof(float));
        const float* Xl = (l == 2) ? coord : xyz;
        if (l == 1) {
            cudaMemsetAsync(xagg, 0, (size_t)NN * 3 * sizeof(float));
            edge_mma_kernel<true><<<nsm, 512, SMEM_EDGE_CO>>>(
                src, dst, Xl, hs, hd, ew1l + 256 * C, e_b1 + l * C,
                e_w2 + (size_t)l * C * C, e_b2 + l * C,
                c_w1 + (size_t)l * C * C, c_b1 + l * C, c_w2 + l * C, hagg, xagg);
        } else {
            edge_mma_kernel<false><<<nsm, 512, SMEM_EDGE_NC>>>(
                src, dst, Xl, hs, hd, ew1l + 256 * C, e_b1 + l * C,
                e_w2 + (size_t)l * C * C, e_b2 + l * C,
                c_w1 + (size_t)l * C * C, c_b1 + l * C, c_w2 + l * C, hagg, xagg);
        }
        if (l == 0)
            node_kernel<false><<<NN / 8, 128>>>(hcur, hagg,
                n_w1 + (size_t)l * 256 * C, n_b1 + l * C,
                n_w2 + (size_t)l * C * C, n_b2 + l * C, dec_ln_g, dec_ln_b, htmp);
        else
            node_kernel<true><<<NN / 8, 128>>>(hcur, hagg,
                n_w1 + (size_t)l * 256 * C, n_b1 + l * C,
                n_w2 + (size_t)l * C * C, n_b2 + l * C, dec_ln_g, dec_ln_b, htmp);
        float* t = hcur; hcur = htmp; htmp = t;
        if (l == 1) coord_add_kernel<<<(NN * 3 + 255) / 256, 256>>>(xyz, xagg, coord);
    }
    out_kernel<<<(NN + 7) / 8, 256>>>(hcur, out_w, out_b, out);
}